// round 1
// baseline (speedup 1.0000x reference)
#include <cuda_runtime.h>
#include <cuda_bf16.h>
#include <cstdint>

// Problem constants (fixed by the dataset)
#define E_MAX 100000
#define T_MAX 200000
#define H 128
#define NR 16
#define NSR 112   // NS*NR = 7*16
#define NB 8

// ---------------- scratch (device globals; no allocations allowed) ----------
__device__ float g_rbfh[(size_t)E_MAX * H];        // rbf @ rbf_W
__device__ float g_h   [(size_t)E_MAX * H];        // x_ji, then accumulator, then ping
__device__ float g_xkj [(size_t)E_MAX * H];        // x_kj, later temp
__device__ float g_tmp [(size_t)E_MAX * H];        // temp
__device__ float g_sbfh[(size_t)T_MAX * NB];       // sbf @ sbf_W
__device__ float g_wbig[(size_t)H * NB * H];       // bil_W transposed to (K=h, N=b*128+o)
__device__ float g_z   [(size_t)E_MAX * NB * H];   // x_kj @ Wbig  (E, 8*128)

__device__ __forceinline__ float silu_f(float v) {
    return v * (1.0f / (1.0f + __expf(-v)));
}

// ---------------- tiled SGEMM with fused epilogue ----------------------------
// C[M,N] = epilogue(A[M,K] @ B[K,N])
// ACT: 0 none, 1 silu, 2 silu(silu)
// HAS_BIAS: add bias[col] pre-activation
// RES: += Rp[row,col] post-activation
// MUL: *= Mp[row,col] post-activation (applied before RES; not used together)
#define BM 128
#define BN 128
#define BK 16

template<int ACT, bool HAS_BIAS, bool RES, bool MUL>
__global__ void __launch_bounds__(256)
gemm_ep(const float* __restrict__ A, const float* __restrict__ B,
        const float* __restrict__ bias, const float* __restrict__ Rp,
        const float* __restrict__ Mp, float* __restrict__ C,
        int M, int N, int K)
{
    __shared__ float As[BK][BM];
    __shared__ float Bs[BK][BN];

    const int tid = threadIdx.x;
    const int tx = tid & 15;        // 16 col-threads
    const int ty = tid >> 4;        // 16 row-threads
    const int rowBase = blockIdx.x * BM;
    const int colBase = blockIdx.y * BN;

    float acc[8][8];
#pragma unroll
    for (int i = 0; i < 8; i++)
#pragma unroll
        for (int j = 0; j < 8; j++) acc[i][j] = 0.0f;

    for (int k0 = 0; k0 < K; k0 += BK) {
        // Load A tile (BM x BK) transposed into As[k][m]; 512 float4, 2/thread
#pragma unroll
        for (int i = 0; i < 2; i++) {
            int idx = tid * 2 + i;          // 0..511
            int r = idx >> 2;               // row in tile 0..127
            int c4 = idx & 3;               // which float4 within BK
            int grow = rowBase + r;
            float4 v = make_float4(0.f, 0.f, 0.f, 0.f);
            if (grow < M)
                v = *reinterpret_cast<const float4*>(&A[(size_t)grow * K + k0 + c4 * 4]);
            As[c4 * 4 + 0][r] = v.x;
            As[c4 * 4 + 1][r] = v.y;
            As[c4 * 4 + 2][r] = v.z;
            As[c4 * 4 + 3][r] = v.w;
        }
        // Load B tile (BK x BN); 512 float4, 2/thread
#pragma unroll
        for (int i = 0; i < 2; i++) {
            int idx = tid * 2 + i;
            int r = idx >> 5;               // 0..15
            int c4 = idx & 31;              // 0..31
            float4 v = *reinterpret_cast<const float4*>(
                &B[(size_t)(k0 + r) * N + colBase + c4 * 4]);
            *reinterpret_cast<float4*>(&Bs[r][c4 * 4]) = v;
        }
        __syncthreads();

#pragma unroll
        for (int kk = 0; kk < BK; kk++) {
            float a[8], b[8];
            *reinterpret_cast<float4*>(&a[0]) = *reinterpret_cast<float4*>(&As[kk][ty * 8]);
            *reinterpret_cast<float4*>(&a[4]) = *reinterpret_cast<float4*>(&As[kk][ty * 8 + 4]);
            *reinterpret_cast<float4*>(&b[0]) = *reinterpret_cast<float4*>(&Bs[kk][tx * 8]);
            *reinterpret_cast<float4*>(&b[4]) = *reinterpret_cast<float4*>(&Bs[kk][tx * 8 + 4]);
#pragma unroll
            for (int i = 0; i < 8; i++)
#pragma unroll
                for (int j = 0; j < 8; j++)
                    acc[i][j] = fmaf(a[i], b[j], acc[i][j]);
        }
        __syncthreads();
    }

    // Epilogue
#pragma unroll
    for (int i = 0; i < 8; i++) {
        int grow = rowBase + ty * 8 + i;
        if (grow >= M) continue;
#pragma unroll
        for (int j = 0; j < 8; j += 4) {
            int gcol = colBase + tx * 8 + j;
            float4 v;
            float* vp = &v.x;
#pragma unroll
            for (int e = 0; e < 4; e++) {
                float t = acc[i][j + e];
                if (HAS_BIAS) t += bias[gcol + e];
                if (ACT >= 1) t = silu_f(t);
                if (ACT == 2) t = silu_f(t);
                if (MUL) t *= Mp[(size_t)grow * N + gcol + e];
                if (RES) t += Rp[(size_t)grow * N + gcol + e];
                vp[e] = t;
            }
            *reinterpret_cast<float4*>(&C[(size_t)grow * N + gcol]) = v;
        }
    }
}

// ---------------- sbf_h = sbf (T,112) @ sbf_W (112,8) -----------------------
__global__ void sbf_kernel(const float* __restrict__ sbf,
                           const float* __restrict__ sbfW,
                           float* __restrict__ out, int T)
{
    __shared__ float Ws[NB][NSR];   // transposed: Ws[o][k]
    for (int i = threadIdx.x; i < NSR * NB; i += blockDim.x) {
        int k = i / NB, o = i % NB;
        Ws[o][k] = sbfW[i];
    }
    __syncthreads();

    int warp = threadIdx.x >> 5;
    int lane = threadIdx.x & 31;
    int t = blockIdx.x * (blockDim.x >> 5) + warp;
    if (t >= T) return;

    const float* srow = sbf + (size_t)t * NSR;
    float acc[NB];
#pragma unroll
    for (int o = 0; o < NB; o++) acc[o] = 0.0f;

    for (int k = lane; k < NSR; k += 32) {
        float s = srow[k];
#pragma unroll
        for (int o = 0; o < NB; o++) acc[o] = fmaf(s, Ws[o][k], acc[o]);
    }
#pragma unroll
    for (int off = 16; off > 0; off >>= 1) {
#pragma unroll
        for (int o = 0; o < NB; o++)
            acc[o] += __shfl_down_sync(0xffffffffu, acc[o], off);
    }
    if (lane < NB) {
        // lane 0 holds all; broadcast via shfl to write coalesced
    }
    if (lane == 0) {
#pragma unroll
        for (int o = 0; o < NB; o++) out[(size_t)t * NB + o] = acc[o];
    }
}

// ---------------- transpose bil_W (o,b,h) -> Wbig[h][b*128+o] ----------------
__global__ void prep_wbig(const float* __restrict__ bilW, float* __restrict__ Wbig)
{
    int idx = blockIdx.x * blockDim.x + threadIdx.x;   // over 128*1024
    if (idx >= H * NB * H) return;
    int k = idx >> 10;          // h  0..127
    int n = idx & 1023;
    int b = n >> 7;
    int o = n & 127;
    Wbig[idx] = bilW[(size_t)o * (NB * H) + b * H + k];
}

// ---------------- triplet gather + scale + scatter-add -----------------------
// m[t,o] = sum_b sbf_h[t,b] * z[kj[t], b, o];  h[ji[t], o] += m[t,o]
__global__ void triplet_scatter(const float* __restrict__ z,
                                const float* __restrict__ sbfh,
                                const int* __restrict__ kj,
                                const int* __restrict__ ji,
                                float* __restrict__ h, int T)
{
    int warp = threadIdx.x >> 5;
    int lane = threadIdx.x & 31;
    int t = blockIdx.x * (blockDim.x >> 5) + warp;
    if (t >= T) return;

    int ekj = kj[t];
    int eji = ji[t];
    float s[NB];
#pragma unroll
    for (int b = 0; b < NB; b++) s[b] = __ldg(&sbfh[(size_t)t * NB + b]);

    const float4* zp = reinterpret_cast<const float4*>(z + (size_t)ekj * (NB * H));
    float4 acc = make_float4(0.f, 0.f, 0.f, 0.f);
#pragma unroll
    for (int b = 0; b < NB; b++) {
        float4 v = __ldg(&zp[b * 32 + lane]);
        acc.x = fmaf(s[b], v.x, acc.x);
        acc.y = fmaf(s[b], v.y, acc.y);
        acc.z = fmaf(s[b], v.z, acc.z);
        acc.w = fmaf(s[b], v.w, acc.w);
    }
    float* dst = h + (size_t)eji * H + lane * 4;
    atomicAdd(dst + 0, acc.x);
    atomicAdd(dst + 1, acc.y);
    atomicAdd(dst + 2, acc.z);
    atomicAdd(dst + 3, acc.w);
}

// ---------------- launch ------------------------------------------------------
extern "C" void kernel_launch(void* const* d_in, const int* in_sizes, int n_in,
                              void* d_out, int out_size)
{
    const float* x      = (const float*)d_in[0];
    const float* rbf    = (const float*)d_in[1];
    const float* sbf    = (const float*)d_in[2];
    const int*   kj     = (const int*)  d_in[3];
    const int*   ji     = (const int*)  d_in[4];
    const float* rbf_W  = (const float*)d_in[5];
    const float* sbf_W  = (const float*)d_in[6];
    const float* ji_W   = (const float*)d_in[7];
    const float* ji_b   = (const float*)d_in[8];
    const float* kj_W   = (const float*)d_in[9];
    const float* kj_b   = (const float*)d_in[10];
    const float* bil_W  = (const float*)d_in[11];
    const float* pre_W1 = (const float*)d_in[12];
    const float* pre_b1 = (const float*)d_in[13];
    const float* pre_W2 = (const float*)d_in[14];
    const float* pre_b2 = (const float*)d_in[15];
    const float* pre_W3 = (const float*)d_in[16];
    const float* pre_b3 = (const float*)d_in[17];
    const float* post_W1 = (const float*)d_in[18];
    const float* post_b1 = (const float*)d_in[19];
    const float* post_W2 = (const float*)d_in[20];
    const float* post_b2 = (const float*)d_in[21];
    const float* post_W3 = (const float*)d_in[22];
    const float* post_b3 = (const float*)d_in[23];
    const float* post_W4 = (const float*)d_in[24];
    const float* post_b4 = (const float*)d_in[25];
    float* out = (float*)d_out;

    const int E = in_sizes[0] / H;
    const int T = in_sizes[3];

    float *p_rbfh, *p_h, *p_xkj, *p_tmp, *p_sbfh, *p_wbig, *p_z;
    cudaGetSymbolAddress((void**)&p_rbfh, g_rbfh);
    cudaGetSymbolAddress((void**)&p_h,    g_h);
    cudaGetSymbolAddress((void**)&p_xkj,  g_xkj);
    cudaGetSymbolAddress((void**)&p_tmp,  g_tmp);
    cudaGetSymbolAddress((void**)&p_sbfh, g_sbfh);
    cudaGetSymbolAddress((void**)&p_wbig, g_wbig);
    cudaGetSymbolAddress((void**)&p_z,    g_z);

    dim3 g1((E + BM - 1) / BM, 1);
    dim3 gz((E + BM - 1) / BM, (NB * H) / BN);

    // rbf_h = rbf @ rbf_W                          (E,16)@(16,128)
    gemm_ep<0, false, false, false><<<g1, 256>>>(rbf, rbf_W, nullptr, nullptr, nullptr,
                                                 p_rbfh, E, H, NR);
    // x_ji = silu(silu(x@ji_W + b))  -> g_h (doubles as scatter accumulator)
    gemm_ep<2, true, false, false><<<g1, 256>>>(x, ji_W, ji_b, nullptr, nullptr,
                                                p_h, E, H, H);
    // x_kj = silu(silu(x@kj_W + b)) * rbf_h
    gemm_ep<2, true, false, true><<<g1, 256>>>(x, kj_W, kj_b, nullptr, p_rbfh,
                                               p_xkj, E, H, H);
    // sbf_h = sbf @ sbf_W
    sbf_kernel<<<(T + 3) / 4, 128>>>(sbf, sbf_W, p_sbfh, T);
    // Wbig = transpose(bil_W)
    prep_wbig<<<(H * NB * H + 255) / 256, 256>>>(bil_W, p_wbig);
    // z = x_kj @ Wbig                              (E,128)@(128,1024)
    gemm_ep<0, false, false, false><<<gz, 256>>>(p_xkj, p_wbig, nullptr, nullptr, nullptr,
                                                 p_z, E, NB * H, H);
    // per-triplet contraction + scatter-add into g_h (which holds x_ji)
    triplet_scatter<<<(T + 7) / 8, 256>>>(p_z, p_sbfh, kj, ji, p_h, T);

    // ---- edge MLP chain ----
    // u = silu(h @ pre_W1 + b1)            -> g_xkj (x_kj dead now)
    gemm_ep<1, true, false, false><<<g1, 256>>>(p_h, pre_W1, pre_b1, nullptr, nullptr,
                                                p_xkj, E, H, H);
    // v = h + silu(u @ pre_W2 + b2)        -> g_tmp
    gemm_ep<1, true, true, false><<<g1, 256>>>(p_xkj, pre_W2, pre_b2, p_h, nullptr,
                                               p_tmp, E, H, H);
    // out0 = silu(v @ pre_W3 + b3) + x     -> g_h
    gemm_ep<1, true, true, false><<<g1, 256>>>(p_tmp, pre_W3, pre_b3, x, nullptr,
                                               p_h, E, H, H);
    // u2 = silu(out0 @ post_W1 + b1)       -> g_xkj
    gemm_ep<1, true, false, false><<<g1, 256>>>(p_h, post_W1, post_b1, nullptr, nullptr,
                                                p_xkj, E, H, H);
    // out1 = out0 + silu(u2 @ post_W2 + b2)-> g_tmp
    gemm_ep<1, true, true, false><<<g1, 256>>>(p_xkj, post_W2, post_b2, p_h, nullptr,
                                               p_tmp, E, H, H);
    // u3 = silu(out1 @ post_W3 + b3)       -> g_xkj
    gemm_ep<1, true, false, false><<<g1, 256>>>(p_tmp, post_W3, post_b3, nullptr, nullptr,
                                                p_xkj, E, H, H);
    // out = out1 + silu(u3 @ post_W4 + b4) -> d_out
    gemm_ep<1, true, true, false><<<g1, 256>>>(p_xkj, post_W4, post_b4, p_tmp, nullptr,
                                               out, E, H, H);
}

// round 3
// speedup vs baseline: 1.3653x; 1.3653x over previous
#include <cuda_runtime.h>
#include <cstdint>

// ---------------- problem constants ----------------
#define E_MAX 100000
#define T_MAX 200000
#define H 128
#define NR 16
#define NSR 112
#define NB 8

// ---------------- scratch ----------------
__device__ float g_rbfh[(size_t)E_MAX * H];
__device__ float g_h   [(size_t)E_MAX * H];
__device__ float g_xkj [(size_t)E_MAX * H];
__device__ float g_tmp [(size_t)E_MAX * H];
__device__ float g_sbfh[(size_t)T_MAX * NB];
__device__ float g_wt  [(size_t)9 * H * H];   // 9 transposed weights [n][k]

// ---------------- helpers ----------------
__device__ __forceinline__ float tf32r(float x) {
    float y; asm("cvt.rna.tf32.f32 %0, %1;" : "=f"(y) : "f"(x)); return y;
}
__device__ __forceinline__ float silu_f(float v) {
    return v * (1.0f / (1.0f + __expf(-v)));
}
// D += A(16x8,row) * B(8x8,col)   tf32 inputs, f32 accum
__device__ __forceinline__ void mma_tf32(float* c, const uint32_t* a, const uint32_t* b) {
    asm volatile(
        "mma.sync.aligned.m16n8k8.row.col.f32.tf32.tf32.f32 "
        "{%0,%1,%2,%3}, {%4,%5,%6,%7}, {%8,%9}, {%0,%1,%2,%3};"
        : "+f"(c[0]), "+f"(c[1]), "+f"(c[2]), "+f"(c[3])
        : "r"(a[0]), "r"(a[1]), "r"(a[2]), "r"(a[3]), "r"(b[0]), "r"(b[1]));
}

// SMEM row pitch (floats) — 132 makes fragment loads conflict-free (4g+t banks)
#define PITCH 132

// ================= TF32 tensor GEMM: C[M,128] = ep(A[M,128] @ Bt[128,128]^T) =====
// Bt is [n][k] (pre-transposed weight). 256 threads, warp grid 2(m)x4(n),
// warp tile 64x32, full K=128 resident in SMEM.
#define TG_SMEM (2 * 128 * PITCH * 4)

template<int ACT, bool HAS_BIAS, bool RES, bool MUL>
__global__ void __launch_bounds__(256, 1)
tgemm(const float* __restrict__ A, const float* __restrict__ Bt,
      const float* __restrict__ bias, const float* __restrict__ Rp,
      const float* __restrict__ Mp, float* __restrict__ C, int M)
{
    extern __shared__ float sm[];
    float* As = sm;                  // [128][PITCH]
    float* Bs = sm + 128 * PITCH;    // [128][PITCH]  (n-major)
    const int tid = threadIdx.x;
    const int wid = tid >> 5, lane = tid & 31;
    const int g = lane >> 2, t4 = lane & 3;
    const int rowBase = blockIdx.x * 128;
    const int mrow = (wid >> 2) * 64;
    const int ncol = (wid & 3) * 32;

    // stage A (tf32-rounded, zero-pad beyond M)
#pragma unroll
    for (int i = 0; i < 16; i++) {
        int idx = i * 256 + tid;
        int r = idx >> 5, c4 = idx & 31;
        int grow = rowBase + r;
        float4 v = make_float4(0.f, 0.f, 0.f, 0.f);
        if (grow < M) v = *(const float4*)&A[(size_t)grow * H + c4 * 4];
        v.x = tf32r(v.x); v.y = tf32r(v.y); v.z = tf32r(v.z); v.w = tf32r(v.w);
        *(float4*)&As[r * PITCH + c4 * 4] = v;
    }
    // stage B
#pragma unroll
    for (int i = 0; i < 16; i++) {
        int idx = i * 256 + tid;
        int r = idx >> 5, c4 = idx & 31;
        float4 v = *(const float4*)&Bt[(size_t)r * H + c4 * 4];
        v.x = tf32r(v.x); v.y = tf32r(v.y); v.z = tf32r(v.z); v.w = tf32r(v.w);
        *(float4*)&Bs[r * PITCH + c4 * 4] = v;
    }
    __syncthreads();

    float acc[4][4][4];
#pragma unroll
    for (int i = 0; i < 4; i++)
#pragma unroll
        for (int j = 0; j < 4; j++)
#pragma unroll
            for (int e = 0; e < 4; e++) acc[i][j][e] = 0.f;

#pragma unroll
    for (int ks = 0; ks < 16; ks++) {
        const int k0 = ks * 8;
        uint32_t a[4][4], b[4][2];
#pragma unroll
        for (int i = 0; i < 4; i++) {
            int r0 = mrow + i * 16 + g;
            a[i][0] = __float_as_uint(As[r0 * PITCH + k0 + t4]);
            a[i][1] = __float_as_uint(As[(r0 + 8) * PITCH + k0 + t4]);
            a[i][2] = __float_as_uint(As[r0 * PITCH + k0 + t4 + 4]);
            a[i][3] = __float_as_uint(As[(r0 + 8) * PITCH + k0 + t4 + 4]);
        }
#pragma unroll
        for (int j = 0; j < 4; j++) {
            int c0 = ncol + j * 8 + g;
            b[j][0] = __float_as_uint(Bs[c0 * PITCH + k0 + t4]);
            b[j][1] = __float_as_uint(Bs[c0 * PITCH + k0 + t4 + 4]);
        }
#pragma unroll
        for (int i = 0; i < 4; i++)
#pragma unroll
            for (int j = 0; j < 4; j++)
                mma_tf32(acc[i][j], a[i], b[j]);
    }

    // epilogue
#pragma unroll
    for (int i = 0; i < 4; i++) {
        int rbase = rowBase + mrow + i * 16 + g;
#pragma unroll
        for (int half = 0; half < 2; half++) {
            int row = rbase + half * 8;
            if (row >= M) continue;
#pragma unroll
            for (int j = 0; j < 4; j++) {
                int col = ncol + j * 8 + t4 * 2;
                float v0 = acc[i][j][half * 2 + 0];
                float v1 = acc[i][j][half * 2 + 1];
                if (HAS_BIAS) { v0 += bias[col]; v1 += bias[col + 1]; }
                if (ACT >= 1) { v0 = silu_f(v0); v1 = silu_f(v1); }
                if (ACT == 2) { v0 = silu_f(v0); v1 = silu_f(v1); }
                if (MUL) {
                    float2 m = *(const float2*)&Mp[(size_t)row * H + col];
                    v0 *= m.x; v1 *= m.y;
                }
                if (RES) {
                    float2 rr = *(const float2*)&Rp[(size_t)row * H + col];
                    v0 += rr.x; v1 += rr.y;
                }
                *(float2*)&C[(size_t)row * H + col] = make_float2(v0, v1);
            }
        }
    }
}

// ================= fused triplet bilinear + scatter ==============================
// m[t,o] = sum_{b,h} sbf_h[t,b]*xkj[kj[t],h]*bilW[o,b,h];  atomicAdd into h[ji[t],o]
// acc registers persist across the 8 bilinear channels; SMEM tiles restaged per b.
#define TRJ   0
#define TRK   512
#define TRS   1024
#define TRRAW 5120
#define TRA   70656
#define TRB   (TRA + 128 * PITCH * 4)
#define TR_SMEM (TRB + 128 * PITCH * 4)

__global__ void __launch_bounds__(256, 1)
triplet_fused(const float* __restrict__ xkj, const float* __restrict__ sbfh,
              const int* __restrict__ kj, const int* __restrict__ ji,
              const float* __restrict__ bilW, float* __restrict__ hout, int T)
{
    extern __shared__ char smem[];
    int* ji_s = (int*)(smem + TRJ);
    int* ek_s = (int*)(smem + TRK);
    float* sbf_s = (float*)(smem + TRS);
    float* raw = (float*)(smem + TRRAW);     // [128][128] gathered x_kj rows (fp32)
    float* As = (float*)(smem + TRA);        // [128][PITCH]
    float* Bs = (float*)(smem + TRB);        // [128][PITCH]
    const int tid = threadIdx.x;
    const int wid = tid >> 5, lane = tid & 31;
    const int g = lane >> 2, t4 = lane & 3;
    const int tBase = blockIdx.x * 128;
    const int mrow = (wid >> 2) * 64;
    const int ncol = (wid & 3) * 32;

    if (tid < 128) {
        int t = tBase + tid;
        ji_s[tid] = (t < T) ? ji[t] : 0;
        ek_s[tid] = (t < T) ? kj[t] : 0;
        float4 a = make_float4(0.f, 0.f, 0.f, 0.f), b = a;
        if (t < T) {
            a = *(const float4*)&sbfh[(size_t)t * NB];
            b = *(const float4*)&sbfh[(size_t)t * NB + 4];
        }
        *(float4*)&sbf_s[tid * NB] = a;
        *(float4*)&sbf_s[tid * NB + 4] = b;
    }
    __syncthreads();
    // gather x_kj rows (mostly L2-resident)
#pragma unroll
    for (int i = 0; i < 16; i++) {
        int idx = i * 256 + tid;
        int r = idx >> 5, c4 = idx & 31;
        int e = ek_s[r];
        *(float4*)&raw[r * H + c4 * 4] = *(const float4*)&xkj[(size_t)e * H + c4 * 4];
    }

    float acc[4][4][4];
#pragma unroll
    for (int i = 0; i < 4; i++)
#pragma unroll
        for (int j = 0; j < 4; j++)
#pragma unroll
            for (int e = 0; e < 4; e++) acc[i][j][e] = 0.f;

    for (int b = 0; b < NB; b++) {
        __syncthreads();   // previous iter's reads done before restaging
        // stage A' = sbf[:,b] * raw   (tf32-rounded)
#pragma unroll
        for (int i = 0; i < 16; i++) {
            int idx = i * 256 + tid;
            int r = idx >> 5, c4 = idx & 31;
            float s = sbf_s[r * NB + b];
            float4 v = *(float4*)&raw[r * H + c4 * 4];
            v.x = tf32r(v.x * s); v.y = tf32r(v.y * s);
            v.z = tf32r(v.z * s); v.w = tf32r(v.w * s);
            *(float4*)&As[r * PITCH + c4 * 4] = v;
        }
        // stage B chunk: bilW[o, b, :]  (already K-contiguous)
#pragma unroll
        for (int i = 0; i < 16; i++) {
            int idx = i * 256 + tid;
            int r = idx >> 5, c4 = idx & 31;
            float4 v = *(const float4*)&bilW[(size_t)r * (NB * H) + b * H + c4 * 4];
            v.x = tf32r(v.x); v.y = tf32r(v.y); v.z = tf32r(v.z); v.w = tf32r(v.w);
            *(float4*)&Bs[r * PITCH + c4 * 4] = v;
        }
        __syncthreads();

#pragma unroll
        for (int ks = 0; ks < 16; ks++) {
            const int k0 = ks * 8;
            uint32_t a[4][4], bb[4][2];
#pragma unroll
            for (int i = 0; i < 4; i++) {
                int r0 = mrow + i * 16 + g;
                a[i][0] = __float_as_uint(As[r0 * PITCH + k0 + t4]);
                a[i][1] = __float_as_uint(As[(r0 + 8) * PITCH + k0 + t4]);
                a[i][2] = __float_as_uint(As[r0 * PITCH + k0 + t4 + 4]);
                a[i][3] = __float_as_uint(As[(r0 + 8) * PITCH + k0 + t4 + 4]);
            }
#pragma unroll
            for (int j = 0; j < 4; j++) {
                int c0 = ncol + j * 8 + g;
                bb[j][0] = __float_as_uint(Bs[c0 * PITCH + k0 + t4]);
                bb[j][1] = __float_as_uint(Bs[c0 * PITCH + k0 + t4 + 4]);
            }
#pragma unroll
            for (int i = 0; i < 4; i++)
#pragma unroll
                for (int j = 0; j < 4; j++)
                    mma_tf32(acc[i][j], a[i], bb[j]);
        }
    }

    // scatter-add epilogue
#pragma unroll
    for (int i = 0; i < 4; i++) {
        int rloc = mrow + i * 16 + g;
#pragma unroll
        for (int half = 0; half < 2; half++) {
            int r = rloc + half * 8;
            int t = tBase + r;
            if (t >= T) continue;
            int e = ji_s[r];
            float* dst = &hout[(size_t)e * H];
#pragma unroll
            for (int j = 0; j < 4; j++) {
                int col = ncol + j * 8 + t4 * 2;
                atomicAdd(dst + col,     acc[i][j][half * 2 + 0]);
                atomicAdd(dst + col + 1, acc[i][j][half * 2 + 1]);
            }
        }
    }
}

// ================= sbf_h = sbf (T,112) @ sbf_W (112,8) ===========================
#define SBF_SMEM (NB * NSR * 4 + 128 * 113 * 4)
__global__ void __launch_bounds__(128)
sbf_fast(const float* __restrict__ sbf, const float* __restrict__ sbfW,
         float* __restrict__ out, int T)
{
    extern __shared__ float sm[];
    float* Ws = sm;                 // [8][112]
    float* tile = sm + NB * NSR;    // [128][113]
    const int tid = threadIdx.x;
    const int t0 = blockIdx.x * 128;
    for (int i = tid; i < NSR * NB; i += 128) {
        int k = i / NB, o = i % NB;
        Ws[o * NSR + k] = sbfW[i];
    }
    for (int i = tid; i < 128 * 28; i += 128) {
        int r = i / 28, c = i % 28;
        int t = t0 + r;
        float4 v = make_float4(0.f, 0.f, 0.f, 0.f);
        if (t < T) v = *(const float4*)&sbf[(size_t)t * NSR + c * 4];
        tile[r * 113 + c * 4 + 0] = v.x;
        tile[r * 113 + c * 4 + 1] = v.y;
        tile[r * 113 + c * 4 + 2] = v.z;
        tile[r * 113 + c * 4 + 3] = v.w;
    }
    __syncthreads();
    const int t = t0 + tid;
    const float* myrow = &tile[tid * 113];
    float acc[NB];
#pragma unroll
    for (int o = 0; o < NB; o++) acc[o] = 0.f;
#pragma unroll 4
    for (int k = 0; k < NSR; k++) {
        float s = myrow[k];
#pragma unroll
        for (int o = 0; o < NB; o++) acc[o] = fmaf(s, Ws[o * NSR + k], acc[o]);
    }
    if (t < T) {
        *(float4*)&out[(size_t)t * NB]     = make_float4(acc[0], acc[1], acc[2], acc[3]);
        *(float4*)&out[(size_t)t * NB + 4] = make_float4(acc[4], acc[5], acc[6], acc[7]);
    }
}

// ================= SIMT GEMM for rbf (K=16) ======================================
__global__ void __launch_bounds__(256)
rbf_gemm(const float* __restrict__ A, const float* __restrict__ B,
         float* __restrict__ C, int M)
{
    __shared__ float As[16][128];
    __shared__ float Bs[16][128];
    const int tid = threadIdx.x;
    const int tx = tid & 15, ty = tid >> 4;
    const int rowBase = blockIdx.x * 128;
    float acc[8][8];
#pragma unroll
    for (int i = 0; i < 8; i++)
#pragma unroll
        for (int j = 0; j < 8; j++) acc[i][j] = 0.0f;
#pragma unroll
    for (int i = 0; i < 2; i++) {
        int idx = tid * 2 + i;
        int r = idx >> 2, c4 = idx & 3;
        int grow = rowBase + r;
        float4 v = make_float4(0.f, 0.f, 0.f, 0.f);
        if (grow < M) v = *(const float4*)&A[(size_t)grow * NR + c4 * 4];
        As[c4 * 4 + 0][r] = v.x; As[c4 * 4 + 1][r] = v.y;
        As[c4 * 4 + 2][r] = v.z; As[c4 * 4 + 3][r] = v.w;
    }
#pragma unroll
    for (int i = 0; i < 2; i++) {
        int idx = tid * 2 + i;
        int r = idx >> 5, c4 = idx & 31;
        *(float4*)&Bs[r][c4 * 4] = *(const float4*)&B[(size_t)r * H + c4 * 4];
    }
    __syncthreads();
#pragma unroll
    for (int kk = 0; kk < 16; kk++) {
        float a[8], b[8];
        *(float4*)&a[0] = *(float4*)&As[kk][ty * 8];
        *(float4*)&a[4] = *(float4*)&As[kk][ty * 8 + 4];
        *(float4*)&b[0] = *(float4*)&Bs[kk][tx * 8];
        *(float4*)&b[4] = *(float4*)&Bs[kk][tx * 8 + 4];
#pragma unroll
        for (int i = 0; i < 8; i++)
#pragma unroll
            for (int j = 0; j < 8; j++) acc[i][j] = fmaf(a[i], b[j], acc[i][j]);
    }
#pragma unroll
    for (int i = 0; i < 8; i++) {
        int grow = rowBase + ty * 8 + i;
        if (grow >= M) continue;
#pragma unroll
        for (int j = 0; j < 8; j += 4) {
            int gcol = tx * 8 + j;
            *(float4*)&C[(size_t)grow * H + gcol] =
                make_float4(acc[i][j], acc[i][j+1], acc[i][j+2], acc[i][j+3]);
        }
    }
}

// ================= weight transpose ==============================================
struct W9 { const float* p[9]; };
__global__ void transpose_w(W9 ws, float* __restrict__ out)
{
    int w = blockIdx.y;
    const float* in = ws.p[w];
    float* o = out + (size_t)w * H * H;
    int idx = blockIdx.x * 256 + threadIdx.x;
    int n = idx >> 7, k = idx & 127;
    o[n * H + k] = in[k * H + n];
}

// ================= launch ========================================================
extern "C" void kernel_launch(void* const* d_in, const int* in_sizes, int n_in,
                              void* d_out, int out_size)
{
    const float* x      = (const float*)d_in[0];
    const float* rbf    = (const float*)d_in[1];
    const float* sbf    = (const float*)d_in[2];
    const int*   kj     = (const int*)  d_in[3];
    const int*   ji     = (const int*)  d_in[4];
    const float* rbf_W  = (const float*)d_in[5];
    const float* sbf_W  = (const float*)d_in[6];
    const float* ji_W   = (const float*)d_in[7];
    const float* ji_b   = (const float*)d_in[8];
    const float* kj_W   = (const float*)d_in[9];
    const float* kj_b   = (const float*)d_in[10];
    const float* bil_W  = (const float*)d_in[11];
    const float* pre_W1 = (const float*)d_in[12];
    const float* pre_b1 = (const float*)d_in[13];
    const float* pre_W2 = (const float*)d_in[14];
    const float* pre_b2 = (const float*)d_in[15];
    const float* pre_W3 = (const float*)d_in[16];
    const float* pre_b3 = (const float*)d_in[17];
    const float* post_W1 = (const float*)d_in[18];
    const float* post_b1 = (const float*)d_in[19];
    const float* post_W2 = (const float*)d_in[20];
    const float* post_b2 = (const float*)d_in[21];
    const float* post_W3 = (const float*)d_in[22];
    const float* post_b3 = (const float*)d_in[23];
    const float* post_W4 = (const float*)d_in[24];
    const float* post_b4 = (const float*)d_in[25];
    float* out = (float*)d_out;

    const int E = in_sizes[0] / H;
    const int T = in_sizes[3];

    float *p_rbfh, *p_h, *p_xkj, *p_tmp, *p_sbfh, *p_wt;
    cudaGetSymbolAddress((void**)&p_rbfh, g_rbfh);
    cudaGetSymbolAddress((void**)&p_h,    g_h);
    cudaGetSymbolAddress((void**)&p_xkj,  g_xkj);
    cudaGetSymbolAddress((void**)&p_tmp,  g_tmp);
    cudaGetSymbolAddress((void**)&p_sbfh, g_sbfh);
    cudaGetSymbolAddress((void**)&p_wt,   g_wt);

    cudaFuncSetAttribute(tgemm<2, true, false, true>,  cudaFuncAttributeMaxDynamicSharedMemorySize, TG_SMEM);
    cudaFuncSetAttribute(tgemm<2, true, false, false>, cudaFuncAttributeMaxDynamicSharedMemorySize, TG_SMEM);
    cudaFuncSetAttribute(tgemm<1, true, false, false>, cudaFuncAttributeMaxDynamicSharedMemorySize, TG_SMEM);
    cudaFuncSetAttribute(tgemm<1, true, true,  false>, cudaFuncAttributeMaxDynamicSharedMemorySize, TG_SMEM);
    cudaFuncSetAttribute(triplet_fused, cudaFuncAttributeMaxDynamicSharedMemorySize, TR_SMEM);
    cudaFuncSetAttribute(sbf_fast, cudaFuncAttributeMaxDynamicSharedMemorySize, SBF_SMEM);

    const int gE = (E + 127) / 128;
    const int gT = (T + 127) / 128;

    // 0. transpose the 9 dense weights to [n][k]
    W9 ws;
    ws.p[0] = ji_W;   ws.p[1] = kj_W;
    ws.p[2] = pre_W1; ws.p[3] = pre_W2; ws.p[4] = pre_W3;
    ws.p[5] = post_W1; ws.p[6] = post_W2; ws.p[7] = post_W3; ws.p[8] = post_W4;
    transpose_w<<<dim3(64, 9), 256>>>(ws, p_wt);

    // 1. rbf_h = rbf @ rbf_W   (SIMT, K=16)
    rbf_gemm<<<gE, 256>>>(rbf, rbf_W, p_rbfh, E);
    // 2. sbf_h = sbf @ sbf_W
    sbf_fast<<<gT, 128, SBF_SMEM>>>(sbf, sbf_W, p_sbfh, T);
    // 3. x_kj = silu(silu(x@kj_W+b)) * rbf_h
    tgemm<2, true, false, true><<<gE, 256, TG_SMEM>>>(x, p_wt + 1 * H * H, kj_b, nullptr, p_rbfh, p_xkj, E);
    // 4. x_ji = silu(silu(x@ji_W+b))   -> g_h (scatter accumulator)
    tgemm<2, true, false, false><<<gE, 256, TG_SMEM>>>(x, p_wt + 0 * H * H, ji_b, nullptr, nullptr, p_h, E);
    // 5. triplet bilinear + scatter-add into g_h
    triplet_fused<<<gT, 256, TR_SMEM>>>(p_xkj, p_sbfh, kj, ji, bil_W, p_h, T);
    // 6..12. edge MLP chain
    tgemm<1, true, false, false><<<gE, 256, TG_SMEM>>>(p_h,   p_wt + 2 * H * H, pre_b1, nullptr, nullptr, p_xkj, E);
    tgemm<1, true, true,  false><<<gE, 256, TG_SMEM>>>(p_xkj, p_wt + 3 * H * H, pre_b2, p_h,    nullptr, p_tmp, E);
    tgemm<1, true, true,  false><<<gE, 256, TG_SMEM>>>(p_tmp, p_wt + 4 * H * H, pre_b3, x,      nullptr, p_h,   E);
    tgemm<1, true, false, false><<<gE, 256, TG_SMEM>>>(p_h,   p_wt + 5 * H * H, post_b1, nullptr, nullptr, p_xkj, E);
    tgemm<1, true, true,  false><<<gE, 256, TG_SMEM>>>(p_xkj, p_wt + 6 * H * H, post_b2, p_h,   nullptr, p_tmp, E);
    tgemm<1, true, false, false><<<gE, 256, TG_SMEM>>>(p_tmp, p_wt + 7 * H * H, post_b3, nullptr, nullptr, p_xkj, E);
    tgemm<1, true, true,  false><<<gE, 256, TG_SMEM>>>(p_xkj, p_wt + 8 * H * H, post_b4, p_tmp, nullptr, out, E);
}

// round 4
// speedup vs baseline: 1.6570x; 1.2136x over previous
#include <cuda_runtime.h>
#include <cstdint>

// ---------------- problem constants ----------------
#define E_MAX 100000
#define T_MAX 200000
#define H 128
#define NR 16
#define NSR 112
#define NB 8

// ---------------- scratch ----------------
__device__ float g_rbfh[(size_t)E_MAX * H];
__device__ float g_h   [(size_t)E_MAX * H];
__device__ float g_xkj [(size_t)E_MAX * H];
__device__ float g_tmp [(size_t)E_MAX * H];
__device__ float g_sbfh[(size_t)T_MAX * NB];
__device__ float g_wt  [(size_t)9 * H * H];      // 9 transposed+rounded weights [n][k]
__device__ float g_bw  [(size_t)H * NB * H];     // tf32-rounded bil_W copy

// ---------------- helpers ----------------
__device__ __forceinline__ float tf32r(float x) {
    float y; asm("cvt.rna.tf32.f32 %0, %1;" : "=f"(y) : "f"(x)); return y;
}
__device__ __forceinline__ float silu_f(float v) {
    return v * (1.0f / (1.0f + __expf(-v)));
}
// D += A(16x8,row) * B(8x8,col)   tf32 inputs, f32 accum
__device__ __forceinline__ void mma_tf32(float* c, const uint32_t* a, const uint32_t* b) {
    asm volatile(
        "mma.sync.aligned.m16n8k8.row.col.f32.tf32.tf32.f32 "
        "{%0,%1,%2,%3}, {%4,%5,%6,%7}, {%8,%9}, {%0,%1,%2,%3};"
        : "+f"(c[0]), "+f"(c[1]), "+f"(c[2]), "+f"(c[3])
        : "r"(a[0]), "r"(a[1]), "r"(a[2]), "r"(a[3]), "r"(b[0]), "r"(b[1]));
}

// pitches ≡ 4 (mod 32) floats -> conflict-free fragment loads (banks 4g+t4)
#define BP 132      // full-K tiles
#define AP 36       // 32-wide A chunks

// ================= TF32 tensor GEMM: C[M,128] = ep(A[M,128] @ Bt[128,128]^T) =====
// 512 threads, warps 4(m) x 4(n), warp tile 32x32. B staged once (L2-hot weight),
// A pipelined in BK=32 chunks with register prefetch.
#define TG_BS   0
#define TG_AS   (128 * BP * 4)
#define TG_SMEM (TG_AS + 2 * 128 * AP * 4)

template<int ACT, bool HAS_BIAS, bool RES, bool MUL>
__global__ void __launch_bounds__(512, 1)
tgemm(const float* __restrict__ A, const float* __restrict__ Bt,
      const float* __restrict__ bias, const float* __restrict__ Rp,
      const float* __restrict__ Mp, float* __restrict__ C, int M)
{
    extern __shared__ char smem[];
    float* Bs = (float*)(smem + TG_BS);              // [128][BP]
    float* As = (float*)(smem + TG_AS);              // [2][128][AP]
    const int tid = threadIdx.x;
    const int wid = tid >> 5, lane = tid & 31;
    const int g = lane >> 2, t4 = lane & 3;
    const int rowBase = blockIdx.x * 128;
    const int mrow = (wid & 3) * 32;
    const int ncol = (wid >> 2) * 32;

    // stage full B (pre-rounded weights)
#pragma unroll
    for (int i = 0; i < 8; i++) {
        int idx = i * 512 + tid;
        int r = idx >> 5, c4 = idx & 31;
        *(float4*)&Bs[r * BP + c4 * 4] = *(const float4*)&Bt[(size_t)r * H + c4 * 4];
    }

    // prefetch + store A chunk 0
    const int ar = (tid * 2) >> 3;       // row handled by this thread (2 float4 -> idx base)
    float4 pa[2];
#pragma unroll
    for (int i = 0; i < 2; i++) {
        int idx = i * 512 + tid;
        int r = idx >> 3, c4 = idx & 7;
        int grow = rowBase + r;
        pa[i] = (grow < M) ? *(const float4*)&A[(size_t)grow * H + c4 * 4]
                           : make_float4(0.f, 0.f, 0.f, 0.f);
    }
#pragma unroll
    for (int i = 0; i < 2; i++) {
        int idx = i * 512 + tid;
        int r = idx >> 3, c4 = idx & 7;
        float4 v = pa[i];
        v.x = tf32r(v.x); v.y = tf32r(v.y); v.z = tf32r(v.z); v.w = tf32r(v.w);
        *(float4*)&As[r * AP + c4 * 4] = v;
    }
    __syncthreads();
    (void)ar;

    float acc[2][4][4];
#pragma unroll
    for (int i = 0; i < 2; i++)
#pragma unroll
        for (int j = 0; j < 4; j++)
#pragma unroll
            for (int e = 0; e < 4; e++) acc[i][j][e] = 0.f;

#pragma unroll
    for (int c = 0; c < 4; c++) {
        if (c < 3) {
#pragma unroll
            for (int i = 0; i < 2; i++) {
                int idx = i * 512 + tid;
                int r = idx >> 3, c4 = idx & 7;
                int grow = rowBase + r;
                pa[i] = (grow < M) ? *(const float4*)&A[(size_t)grow * H + (c + 1) * 32 + c4 * 4]
                                   : make_float4(0.f, 0.f, 0.f, 0.f);
            }
        }
        const float* Ab = &As[(c & 1) * 128 * AP];
#pragma unroll
        for (int ks = 0; ks < 4; ks++) {
            const int k0 = ks * 8;
            uint32_t a[2][4], b[4][2];
#pragma unroll
            for (int i = 0; i < 2; i++) {
                int r0 = mrow + i * 16 + g;
                a[i][0] = __float_as_uint(Ab[r0 * AP + k0 + t4]);
                a[i][1] = __float_as_uint(Ab[(r0 + 8) * AP + k0 + t4]);
                a[i][2] = __float_as_uint(Ab[r0 * AP + k0 + t4 + 4]);
                a[i][3] = __float_as_uint(Ab[(r0 + 8) * AP + k0 + t4 + 4]);
            }
            const int kg = c * 32 + k0;
#pragma unroll
            for (int j = 0; j < 4; j++) {
                int c0 = ncol + j * 8 + g;
                b[j][0] = __float_as_uint(Bs[c0 * BP + kg + t4]);
                b[j][1] = __float_as_uint(Bs[c0 * BP + kg + t4 + 4]);
            }
#pragma unroll
            for (int i = 0; i < 2; i++)
#pragma unroll
                for (int j = 0; j < 4; j++)
                    mma_tf32(acc[i][j], a[i], b[j]);
        }
        __syncthreads();
        if (c < 3) {
            float* An = &As[((c + 1) & 1) * 128 * AP];
#pragma unroll
            for (int i = 0; i < 2; i++) {
                int idx = i * 512 + tid;
                int r = idx >> 3, c4 = idx & 7;
                float4 v = pa[i];
                v.x = tf32r(v.x); v.y = tf32r(v.y); v.z = tf32r(v.z); v.w = tf32r(v.w);
                *(float4*)&An[r * AP + c4 * 4] = v;
            }
            __syncthreads();
        }
    }

    // epilogue
#pragma unroll
    for (int i = 0; i < 2; i++) {
#pragma unroll
        for (int half = 0; half < 2; half++) {
            int row = rowBase + mrow + i * 16 + half * 8 + g;
            if (row >= M) continue;
#pragma unroll
            for (int j = 0; j < 4; j++) {
                int col = ncol + j * 8 + t4 * 2;
                float v0 = acc[i][j][half * 2 + 0];
                float v1 = acc[i][j][half * 2 + 1];
                if (HAS_BIAS) { v0 += bias[col]; v1 += bias[col + 1]; }
                if (ACT >= 1) { v0 = silu_f(v0); v1 = silu_f(v1); }
                if (ACT == 2) { v0 = silu_f(v0); v1 = silu_f(v1); }
                if (MUL) {
                    float2 m = *(const float2*)&Mp[(size_t)row * H + col];
                    v0 *= m.x; v1 *= m.y;
                }
                if (RES) {
                    float2 rr = *(const float2*)&Rp[(size_t)row * H + col];
                    v0 += rr.x; v1 += rr.y;
                }
                *(float2*)&C[(size_t)row * H + col] = make_float2(v0, v1);
            }
        }
    }
}

// ================= fused triplet bilinear + scatter ==============================
// m[t,o] = sum_{b,h} sbf[t,b]*xkj[kj[t],h]*bilW[o,b,h]; atomicAdd into h[ji[t],o].
// A-fragments built on the fly from SMEM-resident gathered rows (raw) * sbf scale.
#define TRJ   0
#define TRK   512
#define TRS   1024
#define TRRAW 5120
#define TRB   (TRRAW + 128 * BP * 4)
#define TR_SMEM (TRB + 128 * BP * 4)

__global__ void __launch_bounds__(512, 1)
triplet_fused(const float* __restrict__ xkj, const float* __restrict__ sbfh,
              const int* __restrict__ kj, const int* __restrict__ ji,
              const float* __restrict__ bw, float* __restrict__ hout, int T)
{
    extern __shared__ char smem[];
    int* ji_s = (int*)(smem + TRJ);
    int* ek_s = (int*)(smem + TRK);
    float* sbf_s = (float*)(smem + TRS);
    float* raw = (float*)(smem + TRRAW);   // [128][BP] gathered x_kj rows (fp32)
    float* Bs = (float*)(smem + TRB);      // [128][BP] current channel of bil_W
    const int tid = threadIdx.x;
    const int wid = tid >> 5, lane = tid & 31;
    const int g = lane >> 2, t4 = lane & 3;
    const int tBase = blockIdx.x * 128;
    const int mrow = (wid & 3) * 32;
    const int ncol = (wid >> 2) * 32;

    if (tid < 128) {
        int t = tBase + tid;
        ji_s[tid] = (t < T) ? ji[t] : 0;
        ek_s[tid] = (t < T) ? kj[t] : 0;
        float4 a = make_float4(0.f, 0.f, 0.f, 0.f), b = a;
        if (t < T) {
            a = *(const float4*)&sbfh[(size_t)t * NB];
            b = *(const float4*)&sbfh[(size_t)t * NB + 4];
        }
        *(float4*)&sbf_s[tid * NB] = a;
        *(float4*)&sbf_s[tid * NB + 4] = b;
    }
    __syncthreads();
    // gather x_kj rows into raw (L2-resident source)
#pragma unroll
    for (int i = 0; i < 8; i++) {
        int idx = i * 512 + tid;
        int r = idx >> 5, c4 = idx & 31;
        int e = ek_s[r];
        *(float4*)&raw[r * BP + c4 * 4] = *(const float4*)&xkj[(size_t)e * H + c4 * 4];
    }

    float acc[2][4][4];
#pragma unroll
    for (int i = 0; i < 2; i++)
#pragma unroll
        for (int j = 0; j < 4; j++)
#pragma unroll
            for (int e = 0; e < 4; e++) acc[i][j][e] = 0.f;

    // per-thread row scales (4 fixed rows in the warp tile)
    const int r0 = mrow + g;

    for (int b = 0; b < NB; b++) {
        __syncthreads();   // prior compute done before Bs overwrite (also covers raw init)
        // stage channel b of bil_W (pre-rounded, L2-hot)
#pragma unroll
        for (int i = 0; i < 8; i++) {
            int idx = i * 512 + tid;
            int r = idx >> 5, c4 = idx & 31;
            *(float4*)&Bs[r * BP + c4 * 4] =
                *(const float4*)&bw[(size_t)r * (NB * H) + b * H + c4 * 4];
        }
        __syncthreads();

        float s0 = sbf_s[(r0)      * NB + b];
        float s1 = sbf_s[(r0 + 8)  * NB + b];
        float s2 = sbf_s[(r0 + 16) * NB + b];
        float s3 = sbf_s[(r0 + 24) * NB + b];

#pragma unroll
        for (int ks = 0; ks < 16; ks++) {
            const int k0 = ks * 8;
            uint32_t a[2][4], bb[4][2];
            a[0][0] = __float_as_uint(tf32r(raw[(r0)      * BP + k0 + t4] * s0));
            a[0][1] = __float_as_uint(tf32r(raw[(r0 + 8)  * BP + k0 + t4] * s1));
            a[0][2] = __float_as_uint(tf32r(raw[(r0)      * BP + k0 + t4 + 4] * s0));
            a[0][3] = __float_as_uint(tf32r(raw[(r0 + 8)  * BP + k0 + t4 + 4] * s1));
            a[1][0] = __float_as_uint(tf32r(raw[(r0 + 16) * BP + k0 + t4] * s2));
            a[1][1] = __float_as_uint(tf32r(raw[(r0 + 24) * BP + k0 + t4] * s3));
            a[1][2] = __float_as_uint(tf32r(raw[(r0 + 16) * BP + k0 + t4 + 4] * s2));
            a[1][3] = __float_as_uint(tf32r(raw[(r0 + 24) * BP + k0 + t4 + 4] * s3));
#pragma unroll
            for (int j = 0; j < 4; j++) {
                int c0 = ncol + j * 8 + g;
                bb[j][0] = __float_as_uint(Bs[c0 * BP + k0 + t4]);
                bb[j][1] = __float_as_uint(Bs[c0 * BP + k0 + t4 + 4]);
            }
#pragma unroll
            for (int i = 0; i < 2; i++)
#pragma unroll
                for (int j = 0; j < 4; j++)
                    mma_tf32(acc[i][j], a[i], bb[j]);
        }
    }

    // scatter-add epilogue
#pragma unroll
    for (int i = 0; i < 2; i++) {
#pragma unroll
        for (int half = 0; half < 2; half++) {
            int r = mrow + i * 16 + half * 8 + g;
            int t = tBase + r;
            if (t >= T) continue;
            float* dst = &hout[(size_t)ji_s[r] * H];
#pragma unroll
            for (int j = 0; j < 4; j++) {
                int col = ncol + j * 8 + t4 * 2;
                atomicAdd(dst + col,     acc[i][j][half * 2 + 0]);
                atomicAdd(dst + col + 1, acc[i][j][half * 2 + 1]);
            }
        }
    }
}

// ================= sbf_h = sbf (T,112) @ sbf_W (112,8) ===========================
#define SBF_SMEM (NB * NSR * 4 + 128 * 113 * 4)
__global__ void __launch_bounds__(128)
sbf_fast(const float* __restrict__ sbf, const float* __restrict__ sbfW,
         float* __restrict__ out, int T)
{
    extern __shared__ float sm[];
    float* Ws = sm;                 // [8][112]
    float* tile = sm + NB * NSR;    // [128][113]
    const int tid = threadIdx.x;
    const int t0 = blockIdx.x * 128;
    for (int i = tid; i < NSR * NB; i += 128) {
        int k = i / NB, o = i % NB;
        Ws[o * NSR + k] = sbfW[i];
    }
    for (int i = tid; i < 128 * 28; i += 128) {
        int r = i / 28, c = i % 28;
        int t = t0 + r;
        float4 v = make_float4(0.f, 0.f, 0.f, 0.f);
        if (t < T) v = *(const float4*)&sbf[(size_t)t * NSR + c * 4];
        tile[r * 113 + c * 4 + 0] = v.x;
        tile[r * 113 + c * 4 + 1] = v.y;
        tile[r * 113 + c * 4 + 2] = v.z;
        tile[r * 113 + c * 4 + 3] = v.w;
    }
    __syncthreads();
    const int t = t0 + tid;
    const float* myrow = &tile[tid * 113];
    float acc[NB];
#pragma unroll
    for (int o = 0; o < NB; o++) acc[o] = 0.f;
#pragma unroll 4
    for (int k = 0; k < NSR; k++) {
        float s = myrow[k];
#pragma unroll
        for (int o = 0; o < NB; o++) acc[o] = fmaf(s, Ws[o * NSR + k], acc[o]);
    }
    if (t < T) {
        *(float4*)&out[(size_t)t * NB]     = make_float4(acc[0], acc[1], acc[2], acc[3]);
        *(float4*)&out[(size_t)t * NB + 4] = make_float4(acc[4], acc[5], acc[6], acc[7]);
    }
}

// ================= SIMT GEMM for rbf (K=16) ======================================
__global__ void __launch_bounds__(256)
rbf_gemm(const float* __restrict__ A, const float* __restrict__ B,
         float* __restrict__ C, int M)
{
    __shared__ float As[16][128];
    __shared__ float Bsh[16][128];
    const int tid = threadIdx.x;
    const int tx = tid & 15, ty = tid >> 4;
    const int rowBase = blockIdx.x * 128;
    float acc[8][8];
#pragma unroll
    for (int i = 0; i < 8; i++)
#pragma unroll
        for (int j = 0; j < 8; j++) acc[i][j] = 0.0f;
#pragma unroll
    for (int i = 0; i < 2; i++) {
        int idx = tid * 2 + i;
        int r = idx >> 2, c4 = idx & 3;
        int grow = rowBase + r;
        float4 v = make_float4(0.f, 0.f, 0.f, 0.f);
        if (grow < M) v = *(const float4*)&A[(size_t)grow * NR + c4 * 4];
        As[c4 * 4 + 0][r] = v.x; As[c4 * 4 + 1][r] = v.y;
        As[c4 * 4 + 2][r] = v.z; As[c4 * 4 + 3][r] = v.w;
    }
#pragma unroll
    for (int i = 0; i < 2; i++) {
        int idx = tid * 2 + i;
        int r = idx >> 5, c4 = idx & 31;
        *(float4*)&Bsh[r][c4 * 4] = *(const float4*)&B[(size_t)r * H + c4 * 4];
    }
    __syncthreads();
#pragma unroll
    for (int kk = 0; kk < 16; kk++) {
        float a[8], b[8];
        *(float4*)&a[0] = *(float4*)&As[kk][ty * 8];
        *(float4*)&a[4] = *(float4*)&As[kk][ty * 8 + 4];
        *(float4*)&b[0] = *(float4*)&Bsh[kk][tx * 8];
        *(float4*)&b[4] = *(float4*)&Bsh[kk][tx * 8 + 4];
#pragma unroll
        for (int i = 0; i < 8; i++)
#pragma unroll
            for (int j = 0; j < 8; j++) acc[i][j] = fmaf(a[i], b[j], acc[i][j]);
    }
#pragma unroll
    for (int i = 0; i < 8; i++) {
        int grow = rowBase + ty * 8 + i;
        if (grow >= M) continue;
#pragma unroll
        for (int j = 0; j < 8; j += 4) {
            int gcol = tx * 8 + j;
            *(float4*)&C[(size_t)grow * H + gcol] =
                make_float4(acc[i][j], acc[i][j+1], acc[i][j+2], acc[i][j+3]);
        }
    }
}

// ================= weight prep ===================================================
struct W9 { const float* p[9]; };
__global__ void transpose_w(W9 ws, float* __restrict__ out)
{
    int w = blockIdx.y;
    const float* in = ws.p[w];
    float* o = out + (size_t)w * H * H;
    int idx = blockIdx.x * 256 + threadIdx.x;
    int n = idx >> 7, k = idx & 127;
    o[n * H + k] = tf32r(in[k * H + n]);
}
__global__ void round_bilw(const float* __restrict__ in, float* __restrict__ out)
{
    int idx = blockIdx.x * 256 + threadIdx.x;
    if (idx < H * NB * H) out[idx] = tf32r(in[idx]);
}

// ================= launch ========================================================
extern "C" void kernel_launch(void* const* d_in, const int* in_sizes, int n_in,
                              void* d_out, int out_size)
{
    const float* x      = (const float*)d_in[0];
    const float* rbf    = (const float*)d_in[1];
    const float* sbf    = (const float*)d_in[2];
    const int*   kj     = (const int*)  d_in[3];
    const int*   ji     = (const int*)  d_in[4];
    const float* rbf_W  = (const float*)d_in[5];
    const float* sbf_W  = (const float*)d_in[6];
    const float* ji_W   = (const float*)d_in[7];
    const float* ji_b   = (const float*)d_in[8];
    const float* kj_W   = (const float*)d_in[9];
    const float* kj_b   = (const float*)d_in[10];
    const float* bil_W  = (const float*)d_in[11];
    const float* pre_W1 = (const float*)d_in[12];
    const float* pre_b1 = (const float*)d_in[13];
    const float* pre_W2 = (const float*)d_in[14];
    const float* pre_b2 = (const float*)d_in[15];
    const float* pre_W3 = (const float*)d_in[16];
    const float* pre_b3 = (const float*)d_in[17];
    const float* post_W1 = (const float*)d_in[18];
    const float* post_b1 = (const float*)d_in[19];
    const float* post_W2 = (const float*)d_in[20];
    const float* post_b2 = (const float*)d_in[21];
    const float* post_W3 = (const float*)d_in[22];
    const float* post_b3 = (const float*)d_in[23];
    const float* post_W4 = (const float*)d_in[24];
    const float* post_b4 = (const float*)d_in[25];
    float* out = (float*)d_out;

    const int E = in_sizes[0] / H;
    const int T = in_sizes[3];

    float *p_rbfh, *p_h, *p_xkj, *p_tmp, *p_sbfh, *p_wt, *p_bw;
    cudaGetSymbolAddress((void**)&p_rbfh, g_rbfh);
    cudaGetSymbolAddress((void**)&p_h,    g_h);
    cudaGetSymbolAddress((void**)&p_xkj,  g_xkj);
    cudaGetSymbolAddress((void**)&p_tmp,  g_tmp);
    cudaGetSymbolAddress((void**)&p_sbfh, g_sbfh);
    cudaGetSymbolAddress((void**)&p_wt,   g_wt);
    cudaGetSymbolAddress((void**)&p_bw,   g_bw);

    cudaFuncSetAttribute(tgemm<2, true, false, true>,  cudaFuncAttributeMaxDynamicSharedMemorySize, TG_SMEM);
    cudaFuncSetAttribute(tgemm<2, true, false, false>, cudaFuncAttributeMaxDynamicSharedMemorySize, TG_SMEM);
    cudaFuncSetAttribute(tgemm<1, true, false, false>, cudaFuncAttributeMaxDynamicSharedMemorySize, TG_SMEM);
    cudaFuncSetAttribute(tgemm<1, true, true,  false>, cudaFuncAttributeMaxDynamicSharedMemorySize, TG_SMEM);
    cudaFuncSetAttribute(triplet_fused, cudaFuncAttributeMaxDynamicSharedMemorySize, TR_SMEM);
    cudaFuncSetAttribute(sbf_fast, cudaFuncAttributeMaxDynamicSharedMemorySize, SBF_SMEM);

    const int gE = (E + 127) / 128;
    const int gT = (T + 127) / 128;

    // 0. weight prep (transpose+round dense; round bilW)
    W9 ws;
    ws.p[0] = ji_W;   ws.p[1] = kj_W;
    ws.p[2] = pre_W1; ws.p[3] = pre_W2; ws.p[4] = pre_W3;
    ws.p[5] = post_W1; ws.p[6] = post_W2; ws.p[7] = post_W3; ws.p[8] = post_W4;
    transpose_w<<<dim3(64, 9), 256>>>(ws, p_wt);
    round_bilw<<<(H * NB * H + 255) / 256, 256>>>(bil_W, p_bw);

    // 1. rbf_h = rbf @ rbf_W   (SIMT, K=16)
    rbf_gemm<<<gE, 256>>>(rbf, rbf_W, p_rbfh, E);
    // 2. sbf_h = sbf @ sbf_W
    sbf_fast<<<gT, 128, SBF_SMEM>>>(sbf, sbf_W, p_sbfh, T);
    // 3. x_kj = silu(silu(x@kj_W+b)) * rbf_h
    tgemm<2, true, false, true><<<gE, 512, TG_SMEM>>>(x, p_wt + 1 * H * H, kj_b, nullptr, p_rbfh, p_xkj, E);
    // 4. x_ji = silu(silu(x@ji_W+b))   -> g_h (scatter accumulator)
    tgemm<2, true, false, false><<<gE, 512, TG_SMEM>>>(x, p_wt + 0 * H * H, ji_b, nullptr, nullptr, p_h, E);
    // 5. triplet bilinear + scatter-add into g_h
    triplet_fused<<<gT, 512, TR_SMEM>>>(p_xkj, p_sbfh, kj, ji, p_bw, p_h, T);
    // 6..12. edge MLP chain
    tgemm<1, true, false, false><<<gE, 512, TG_SMEM>>>(p_h,   p_wt + 2 * H * H, pre_b1, nullptr, nullptr, p_xkj, E);
    tgemm<1, true, true,  false><<<gE, 512, TG_SMEM>>>(p_xkj, p_wt + 3 * H * H, pre_b2, p_h,    nullptr, p_tmp, E);
    tgemm<1, true, true,  false><<<gE, 512, TG_SMEM>>>(p_tmp, p_wt + 4 * H * H, pre_b3, x,      nullptr, p_h,   E);
    tgemm<1, true, false, false><<<gE, 512, TG_SMEM>>>(p_h,   p_wt + 5 * H * H, post_b1, nullptr, nullptr, p_xkj, E);
    tgemm<1, true, true,  false><<<gE, 512, TG_SMEM>>>(p_xkj, p_wt + 6 * H * H, post_b2, p_h,   nullptr, p_tmp, E);
    tgemm<1, true, false, false><<<gE, 512, TG_SMEM>>>(p_tmp, p_wt + 7 * H * H, post_b3, nullptr, nullptr, p_xkj, E);
    tgemm<1, true, true,  false><<<gE, 512, TG_SMEM>>>(p_xkj, p_wt + 8 * H * H, post_b4, p_tmp, nullptr, out, E);
}

// round 5
// speedup vs baseline: 2.0334x; 1.2271x over previous
#include <cuda_runtime.h>
#include <cstdint>

// ---------------- problem constants ----------------
#define E_MAX 100000
#define T_MAX 200000
#define H 128
#define NR 16
#define NSR 112
#define NB 8

// ---------------- scratch ----------------
__device__ float g_h   [(size_t)E_MAX * H];
__device__ float g_xkj [(size_t)E_MAX * H];
__device__ float g_sbfh[(size_t)T_MAX * NB];
__device__ float g_wt  [(size_t)9 * H * H];      // 9 transposed+rounded weights [n][k]
__device__ float g_bw  [(size_t)H * NB * H];     // tf32-rounded bil_W copy

// ---------------- helpers ----------------
__device__ __forceinline__ float tf32r(float x) {
    float y; asm("cvt.rna.tf32.f32 %0, %1;" : "=f"(y) : "f"(x)); return y;
}
__device__ __forceinline__ uint32_t cvu(float x) { return __float_as_uint(tf32r(x)); }
__device__ __forceinline__ float silu_f(float v) {
    return v * (1.0f / (1.0f + __expf(-v)));
}
__device__ __forceinline__ void mma_tf32(float* c, const uint32_t* a, const uint32_t* b) {
    asm volatile(
        "mma.sync.aligned.m16n8k8.row.col.f32.tf32.tf32.f32 "
        "{%0,%1,%2,%3}, {%4,%5,%6,%7}, {%8,%9}, {%0,%1,%2,%3};"
        : "+f"(c[0]), "+f"(c[1]), "+f"(c[2]), "+f"(c[3])
        : "r"(a[0]), "r"(a[1]), "r"(a[2]), "r"(a[3]), "r"(b[0]), "r"(b[1]));
}

#define BP 132      // tile pitch (floats), 132 % 32 == 4 -> conflict-free frags
#define TILE_B (128 * BP * 4)   // 67584 bytes

// ---------------- shared GEMM building blocks (512 thr, warps 4m x 4n) ----------
__device__ __forceinline__ void acc_zero(float acc[2][4][4]) {
#pragma unroll
    for (int i = 0; i < 2; i++)
#pragma unroll
        for (int j = 0; j < 4; j++)
#pragma unroll
            for (int e = 0; e < 4; e++) acc[i][j][e] = 0.f;
}

// acc += At(128x128 fp32, rounded on the fly) @ Bs(128x128 [n][k], pre-rounded)^T
__device__ __forceinline__ void mma_128(const float* __restrict__ At,
                                        const float* __restrict__ Bs,
                                        float acc[2][4][4],
                                        int r0, int ncol, int g, int t4)
{
#pragma unroll
    for (int ks = 0; ks < 16; ks++) {
        const int k0 = ks * 8;
        uint32_t a[2][4], bb[4][2];
        a[0][0] = cvu(At[(r0)      * BP + k0 + t4]);
        a[0][1] = cvu(At[(r0 + 8)  * BP + k0 + t4]);
        a[0][2] = cvu(At[(r0)      * BP + k0 + t4 + 4]);
        a[0][3] = cvu(At[(r0 + 8)  * BP + k0 + t4 + 4]);
        a[1][0] = cvu(At[(r0 + 16) * BP + k0 + t4]);
        a[1][1] = cvu(At[(r0 + 24) * BP + k0 + t4]);
        a[1][2] = cvu(At[(r0 + 16) * BP + k0 + t4 + 4]);
        a[1][3] = cvu(At[(r0 + 24) * BP + k0 + t4 + 4]);
#pragma unroll
        for (int j = 0; j < 4; j++) {
            int c0 = ncol + j * 8 + g;
            bb[j][0] = __float_as_uint(Bs[c0 * BP + k0 + t4]);
            bb[j][1] = __float_as_uint(Bs[c0 * BP + k0 + t4 + 4]);
        }
#pragma unroll
        for (int i = 0; i < 2; i++)
#pragma unroll
            for (int j = 0; j < 4; j++)
                mma_tf32(acc[i][j], a[i], bb[j]);
    }
}

__device__ __forceinline__ void stage_w(float* Bs, const float* __restrict__ W, int tid) {
#pragma unroll
    for (int i = 0; i < 8; i++) {
        int idx = i * 512 + tid;
        int r = idx >> 5, c4 = idx & 31;
        *(float4*)&Bs[r * BP + c4 * 4] = *(const float4*)&W[(size_t)r * H + c4 * 4];
    }
}
__device__ __forceinline__ void stage_tile(float* Tt, const float* __restrict__ A,
                                           int rowBase, int M, int tid) {
#pragma unroll
    for (int i = 0; i < 8; i++) {
        int idx = i * 512 + tid;
        int r = idx >> 5, c4 = idx & 31;
        int grow = rowBase + r;
        float4 v = (grow < M) ? *(const float4*)&A[(size_t)grow * H + c4 * 4]
                              : make_float4(0.f, 0.f, 0.f, 0.f);
        *(float4*)&Tt[r * BP + c4 * 4] = v;
    }
}
// tile <- silu(acc + bias)
__device__ __forceinline__ void epi_to_tile(float* Tt, const float acc[2][4][4],
                                            const float* biasS,
                                            int mrow, int ncol, int g, int t4)
{
#pragma unroll
    for (int i = 0; i < 2; i++)
#pragma unroll
        for (int half = 0; half < 2; half++) {
            int row = mrow + i * 16 + half * 8 + g;
#pragma unroll
            for (int j = 0; j < 4; j++) {
                int col = ncol + j * 8 + t4 * 2;
                float v0 = silu_f(acc[i][j][half * 2 + 0] + biasS[col]);
                float v1 = silu_f(acc[i][j][half * 2 + 1] + biasS[col + 1]);
                *(float2*)&Tt[row * BP + col] = make_float2(v0, v1);
            }
        }
}

// ================= fused x_ji / x_kj / rbf_h kernel ==============================
#define FJ_T0   0
#define FJ_BS   TILE_B
#define FJ_RB   (2 * TILE_B)
#define FJ_BIAS (3 * TILE_B)
#define FJ_SMEM (FJ_BIAS + 1024)
#define RP 20

__global__ void __launch_bounds__(512, 1)
fused_jikj(const float* __restrict__ x, const float* __restrict__ rbf,
           const float* __restrict__ rbfW,
           const float* __restrict__ kjWt, const float* __restrict__ kjb,
           const float* __restrict__ jiWt, const float* __restrict__ jib,
           float* __restrict__ xkj_out, float* __restrict__ h_out, int M)
{
    extern __shared__ char smem[];
    float* T0 = (float*)(smem + FJ_T0);
    float* Bs = (float*)(smem + FJ_BS);
    float* RB = (float*)(smem + FJ_RB);
    float* bKj = (float*)(smem + FJ_BIAS);
    float* bJi = (float*)(smem + FJ_BIAS + 512);
    float* rtile = Bs;                  // [128][RP] (temp, before kj weight staged)
    float* rw    = Bs + 128 * RP;       // [128][RP]
    const int tid = threadIdx.x;
    const int wid = tid >> 5, lane = tid & 31;
    const int g = lane >> 2, t4 = lane & 3;
    const int rowBase = blockIdx.x * 128;
    const int mrow = (wid & 3) * 32;
    const int ncol = (wid >> 2) * 32;
    const int r0 = mrow + g;

    stage_tile(T0, x, rowBase, M, tid);
    // rbf A tile [128][16] (pitch RP)
    {
        int r = tid >> 2, c4 = tid & 3;
        int grow = rowBase + r;
        float4 v = (grow < M) ? *(const float4*)&rbf[(size_t)grow * NR + c4 * 4]
                              : make_float4(0.f, 0.f, 0.f, 0.f);
        *(float4*)&rtile[r * RP + c4 * 4] = v;
    }
    // rbf_W^T: rw[n*RP + k] = rbfW[k*128 + n]
    {
        int n = tid >> 2, k0 = (tid & 3) * 4;
#pragma unroll
        for (int e = 0; e < 4; e++)
            rw[n * RP + k0 + e] = rbfW[(size_t)(k0 + e) * H + n];
    }
    if (tid < 32)       *(float4*)&bKj[tid * 4] = *(const float4*)&kjb[tid * 4];
    else if (tid < 64)  *(float4*)&bJi[(tid - 32) * 4] = *(const float4*)&jib[(tid - 32) * 4];
    __syncthreads();

    // rbf_h tile = rbf @ rbf_W   (K=16, 2 ks steps)
    float acc[2][4][4];
    acc_zero(acc);
#pragma unroll
    for (int ks = 0; ks < 2; ks++) {
        const int k0 = ks * 8;
        uint32_t a[2][4], bb[4][2];
        a[0][0] = cvu(rtile[(r0)      * RP + k0 + t4]);
        a[0][1] = cvu(rtile[(r0 + 8)  * RP + k0 + t4]);
        a[0][2] = cvu(rtile[(r0)      * RP + k0 + t4 + 4]);
        a[0][3] = cvu(rtile[(r0 + 8)  * RP + k0 + t4 + 4]);
        a[1][0] = cvu(rtile[(r0 + 16) * RP + k0 + t4]);
        a[1][1] = cvu(rtile[(r0 + 24) * RP + k0 + t4]);
        a[1][2] = cvu(rtile[(r0 + 16) * RP + k0 + t4 + 4]);
        a[1][3] = cvu(rtile[(r0 + 24) * RP + k0 + t4 + 4]);
#pragma unroll
        for (int j = 0; j < 4; j++) {
            int c0 = ncol + j * 8 + g;
            bb[j][0] = cvu(rw[c0 * RP + k0 + t4]);
            bb[j][1] = cvu(rw[c0 * RP + k0 + t4 + 4]);
        }
#pragma unroll
        for (int i = 0; i < 2; i++)
#pragma unroll
            for (int j = 0; j < 4; j++)
                mma_tf32(acc[i][j], a[i], bb[j]);
    }
    __syncthreads();   // done reading rtile/rw (Bs region)

    // write rbf_h to RB tile; stage kj weight
#pragma unroll
    for (int i = 0; i < 2; i++)
#pragma unroll
        for (int half = 0; half < 2; half++) {
            int row = mrow + i * 16 + half * 8 + g;
#pragma unroll
            for (int j = 0; j < 4; j++) {
                int col = ncol + j * 8 + t4 * 2;
                *(float2*)&RB[row * BP + col] =
                    make_float2(acc[i][j][half * 2], acc[i][j][half * 2 + 1]);
            }
        }
    stage_w(Bs, kjWt, tid);
    __syncthreads();

    // x_kj = silu(silu(x@kjW+b)) * rbf_h
    acc_zero(acc);
    mma_128(T0, Bs, acc, r0, ncol, g, t4);
#pragma unroll
    for (int i = 0; i < 2; i++)
#pragma unroll
        for (int half = 0; half < 2; half++) {
            int row = mrow + i * 16 + half * 8 + g;
            int grow = rowBase + row;
            if (grow >= M) continue;
#pragma unroll
            for (int j = 0; j < 4; j++) {
                int col = ncol + j * 8 + t4 * 2;
                float v0 = silu_f(silu_f(acc[i][j][half * 2 + 0] + bKj[col]));
                float v1 = silu_f(silu_f(acc[i][j][half * 2 + 1] + bKj[col + 1]));
                float2 m = *(float2*)&RB[row * BP + col];
                *(float2*)&xkj_out[(size_t)grow * H + col] = make_float2(v0 * m.x, v1 * m.y);
            }
        }
    __syncthreads();
    stage_w(Bs, jiWt, tid);
    __syncthreads();

    // x_ji = silu(silu(x@jiW+b))
    acc_zero(acc);
    mma_128(T0, Bs, acc, r0, ncol, g, t4);
#pragma unroll
    for (int i = 0; i < 2; i++)
#pragma unroll
        for (int half = 0; half < 2; half++) {
            int row = mrow + i * 16 + half * 8 + g;
            int grow = rowBase + row;
            if (grow >= M) continue;
#pragma unroll
            for (int j = 0; j < 4; j++) {
                int col = ncol + j * 8 + t4 * 2;
                float v0 = silu_f(silu_f(acc[i][j][half * 2 + 0] + bJi[col]));
                float v1 = silu_f(silu_f(acc[i][j][half * 2 + 1] + bJi[col + 1]));
                *(float2*)&h_out[(size_t)grow * H + col] = make_float2(v0, v1);
            }
        }
}

// ================= fused pre-chain: 3 GEMMs ======================================
#define FP_T0   0
#define FP_T1   TILE_B
#define FP_BS   (2 * TILE_B)
#define FP_BIAS (3 * TILE_B)
#define FP_SMEM (FP_BIAS + 2048)

__global__ void __launch_bounds__(512, 1)
fused_pre(const float* __restrict__ h, const float* __restrict__ x,
          const float* __restrict__ W1t, const float* __restrict__ b1,
          const float* __restrict__ W2t, const float* __restrict__ b2,
          const float* __restrict__ W3t, const float* __restrict__ b3,
          float* __restrict__ outg, int M)
{
    extern __shared__ char smem[];
    float* T0 = (float*)(smem + FP_T0);
    float* T1 = (float*)(smem + FP_T1);
    float* Bs = (float*)(smem + FP_BS);
    float* bS1 = (float*)(smem + FP_BIAS);
    float* bS2 = bS1 + 128;
    float* bS3 = bS2 + 128;
    const int tid = threadIdx.x;
    const int wid = tid >> 5, lane = tid & 31;
    const int g = lane >> 2, t4 = lane & 3;
    const int rowBase = blockIdx.x * 128;
    const int mrow = (wid & 3) * 32;
    const int ncol = (wid >> 2) * 32;
    const int r0 = mrow + g;

    stage_tile(T0, h, rowBase, M, tid);
    if (tid < 32)       *(float4*)&bS1[tid * 4] = *(const float4*)&b1[tid * 4];
    else if (tid < 64)  *(float4*)&bS2[(tid - 32) * 4] = *(const float4*)&b2[(tid - 32) * 4];
    else if (tid < 96)  *(float4*)&bS3[(tid - 64) * 4] = *(const float4*)&b3[(tid - 64) * 4];
    stage_w(Bs, W1t, tid);
    __syncthreads();

    float acc[2][4][4];
    acc_zero(acc);
    mma_128(T0, Bs, acc, r0, ncol, g, t4);
    __syncthreads();
    epi_to_tile(T1, acc, bS1, mrow, ncol, g, t4);        // u
    stage_w(Bs, W2t, tid);
    __syncthreads();

    acc_zero(acc);
    mma_128(T1, Bs, acc, r0, ncol, g, t4);
    __syncthreads();
    // v = h + silu(u@W2+b2)  -> T1
#pragma unroll
    for (int i = 0; i < 2; i++)
#pragma unroll
        for (int half = 0; half < 2; half++) {
            int row = mrow + i * 16 + half * 8 + g;
#pragma unroll
            for (int j = 0; j < 4; j++) {
                int col = ncol + j * 8 + t4 * 2;
                float2 res = *(float2*)&T0[row * BP + col];
                float v0 = res.x + silu_f(acc[i][j][half * 2 + 0] + bS2[col]);
                float v1 = res.y + silu_f(acc[i][j][half * 2 + 1] + bS2[col + 1]);
                *(float2*)&T1[row * BP + col] = make_float2(v0, v1);
            }
        }
    stage_w(Bs, W3t, tid);
    __syncthreads();

    acc_zero(acc);
    mma_128(T1, Bs, acc, r0, ncol, g, t4);
    // out0 = silu(v@W3+b3) + x
#pragma unroll
    for (int i = 0; i < 2; i++)
#pragma unroll
        for (int half = 0; half < 2; half++) {
            int row = mrow + i * 16 + half * 8 + g;
            int grow = rowBase + row;
            if (grow >= M) continue;
#pragma unroll
            for (int j = 0; j < 4; j++) {
                int col = ncol + j * 8 + t4 * 2;
                float2 xr = *(const float2*)&x[(size_t)grow * H + col];
                float v0 = silu_f(acc[i][j][half * 2 + 0] + bS3[col]) + xr.x;
                float v1 = silu_f(acc[i][j][half * 2 + 1] + bS3[col + 1]) + xr.y;
                *(float2*)&outg[(size_t)grow * H + col] = make_float2(v0, v1);
            }
        }
}

// ================= fused post-chain: 4 GEMMs =====================================
__global__ void __launch_bounds__(512, 1)
fused_post(const float* __restrict__ h,
           const float* __restrict__ W1t, const float* __restrict__ b1,
           const float* __restrict__ W2t, const float* __restrict__ b2,
           const float* __restrict__ W3t, const float* __restrict__ b3,
           const float* __restrict__ W4t, const float* __restrict__ b4,
           float* __restrict__ outg, int M)
{
    extern __shared__ char smem[];
    float* T0 = (float*)(smem + FP_T0);
    float* T1 = (float*)(smem + FP_T1);
    float* Bs = (float*)(smem + FP_BS);
    float* bS1 = (float*)(smem + FP_BIAS);
    float* bS2 = bS1 + 128;
    float* bS3 = bS2 + 128;
    float* bS4 = bS3 + 128;
    const int tid = threadIdx.x;
    const int wid = tid >> 5, lane = tid & 31;
    const int g = lane >> 2, t4 = lane & 3;
    const int rowBase = blockIdx.x * 128;
    const int mrow = (wid & 3) * 32;
    const int ncol = (wid >> 2) * 32;
    const int r0 = mrow + g;

    stage_tile(T0, h, rowBase, M, tid);
    if (tid < 32)       *(float4*)&bS1[tid * 4] = *(const float4*)&b1[tid * 4];
    else if (tid < 64)  *(float4*)&bS2[(tid - 32) * 4] = *(const float4*)&b2[(tid - 32) * 4];
    else if (tid < 96)  *(float4*)&bS3[(tid - 64) * 4] = *(const float4*)&b3[(tid - 64) * 4];
    else if (tid < 128) *(float4*)&bS4[(tid - 96) * 4] = *(const float4*)&b4[(tid - 96) * 4];
    stage_w(Bs, W1t, tid);
    __syncthreads();

    float acc[2][4][4];
    acc_zero(acc);
    mma_128(T0, Bs, acc, r0, ncol, g, t4);
    __syncthreads();
    epi_to_tile(T1, acc, bS1, mrow, ncol, g, t4);        // u2
    stage_w(Bs, W2t, tid);
    __syncthreads();

    acc_zero(acc);
    mma_128(T1, Bs, acc, r0, ncol, g, t4);
    __syncthreads();
    // out1 = out0 + silu(u2@W2+b2)  -> overwrite T0 (own slots only)
#pragma unroll
    for (int i = 0; i < 2; i++)
#pragma unroll
        for (int half = 0; half < 2; half++) {
            int row = mrow + i * 16 + half * 8 + g;
#pragma unroll
            for (int j = 0; j < 4; j++) {
                int col = ncol + j * 8 + t4 * 2;
                float2 res = *(float2*)&T0[row * BP + col];
                float v0 = res.x + silu_f(acc[i][j][half * 2 + 0] + bS2[col]);
                float v1 = res.y + silu_f(acc[i][j][half * 2 + 1] + bS2[col + 1]);
                *(float2*)&T0[row * BP + col] = make_float2(v0, v1);
            }
        }
    stage_w(Bs, W3t, tid);
    __syncthreads();

    acc_zero(acc);
    mma_128(T0, Bs, acc, r0, ncol, g, t4);
    __syncthreads();
    epi_to_tile(T1, acc, bS3, mrow, ncol, g, t4);        // u3
    stage_w(Bs, W4t, tid);
    __syncthreads();

    acc_zero(acc);
    mma_128(T1, Bs, acc, r0, ncol, g, t4);
    // out = out1 + silu(u3@W4+b4)
#pragma unroll
    for (int i = 0; i < 2; i++)
#pragma unroll
        for (int half = 0; half < 2; half++) {
            int row = mrow + i * 16 + half * 8 + g;
            int grow = rowBase + row;
            if (grow >= M) continue;
#pragma unroll
            for (int j = 0; j < 4; j++) {
                int col = ncol + j * 8 + t4 * 2;
                float2 res = *(float2*)&T0[row * BP + col];
                float v0 = res.x + silu_f(acc[i][j][half * 2 + 0] + bS4[col]);
                float v1 = res.y + silu_f(acc[i][j][half * 2 + 1] + bS4[col + 1]);
                *(float2*)&outg[(size_t)grow * H + col] = make_float2(v0, v1);
            }
        }
}

// ================= fused triplet bilinear + scatter (unchanged from R4) ==========
#define TRJ   0
#define TRK   512
#define TRS   1024
#define TRRAW 5120
#define TRB   (TRRAW + 128 * BP * 4)
#define TR_SMEM (TRB + 128 * BP * 4)

__global__ void __launch_bounds__(512, 1)
triplet_fused(const float* __restrict__ xkj, const float* __restrict__ sbfh,
              const int* __restrict__ kj, const int* __restrict__ ji,
              const float* __restrict__ bw, float* __restrict__ hout, int T)
{
    extern __shared__ char smem[];
    int* ji_s = (int*)(smem + TRJ);
    int* ek_s = (int*)(smem + TRK);
    float* sbf_s = (float*)(smem + TRS);
    float* raw = (float*)(smem + TRRAW);
    float* Bs = (float*)(smem + TRB);
    const int tid = threadIdx.x;
    const int wid = tid >> 5, lane = tid & 31;
    const int g = lane >> 2, t4 = lane & 3;
    const int tBase = blockIdx.x * 128;
    const int mrow = (wid & 3) * 32;
    const int ncol = (wid >> 2) * 32;

    if (tid < 128) {
        int t = tBase + tid;
        ji_s[tid] = (t < T) ? ji[t] : 0;
        ek_s[tid] = (t < T) ? kj[t] : 0;
        float4 a = make_float4(0.f, 0.f, 0.f, 0.f), b = a;
        if (t < T) {
            a = *(const float4*)&sbfh[(size_t)t * NB];
            b = *(const float4*)&sbfh[(size_t)t * NB + 4];
        }
        *(float4*)&sbf_s[tid * NB] = a;
        *(float4*)&sbf_s[tid * NB + 4] = b;
    }
    __syncthreads();
#pragma unroll
    for (int i = 0; i < 8; i++) {
        int idx = i * 512 + tid;
        int r = idx >> 5, c4 = idx & 31;
        int e = ek_s[r];
        *(float4*)&raw[r * BP + c4 * 4] = *(const float4*)&xkj[(size_t)e * H + c4 * 4];
    }

    float acc[2][4][4];
    acc_zero(acc);
    const int r0 = mrow + g;

    for (int b = 0; b < NB; b++) {
        __syncthreads();
#pragma unroll
        for (int i = 0; i < 8; i++) {
            int idx = i * 512 + tid;
            int r = idx >> 5, c4 = idx & 31;
            *(float4*)&Bs[r * BP + c4 * 4] =
                *(const float4*)&bw[(size_t)r * (NB * H) + b * H + c4 * 4];
        }
        __syncthreads();

        float s0 = sbf_s[(r0)      * NB + b];
        float s1 = sbf_s[(r0 + 8)  * NB + b];
        float s2 = sbf_s[(r0 + 16) * NB + b];
        float s3 = sbf_s[(r0 + 24) * NB + b];

#pragma unroll
        for (int ks = 0; ks < 16; ks++) {
            const int k0 = ks * 8;
            uint32_t a[2][4], bb[4][2];
            a[0][0] = cvu(raw[(r0)      * BP + k0 + t4] * s0);
            a[0][1] = cvu(raw[(r0 + 8)  * BP + k0 + t4] * s1);
            a[0][2] = cvu(raw[(r0)      * BP + k0 + t4 + 4] * s0);
            a[0][3] = cvu(raw[(r0 + 8)  * BP + k0 + t4 + 4] * s1);
            a[1][0] = cvu(raw[(r0 + 16) * BP + k0 + t4] * s2);
            a[1][1] = cvu(raw[(r0 + 24) * BP + k0 + t4] * s3);
            a[1][2] = cvu(raw[(r0 + 16) * BP + k0 + t4 + 4] * s2);
            a[1][3] = cvu(raw[(r0 + 24) * BP + k0 + t4 + 4] * s3);
#pragma unroll
            for (int j = 0; j < 4; j++) {
                int c0 = ncol + j * 8 + g;
                bb[j][0] = __float_as_uint(Bs[c0 * BP + k0 + t4]);
                bb[j][1] = __float_as_uint(Bs[c0 * BP + k0 + t4 + 4]);
            }
#pragma unroll
            for (int i = 0; i < 2; i++)
#pragma unroll
                for (int j = 0; j < 4; j++)
                    mma_tf32(acc[i][j], a[i], bb[j]);
        }
    }

#pragma unroll
    for (int i = 0; i < 2; i++) {
#pragma unroll
        for (int half = 0; half < 2; half++) {
            int r = mrow + i * 16 + half * 8 + g;
            int t = tBase + r;
            if (t >= T) continue;
            float* dst = &hout[(size_t)ji_s[r] * H];
#pragma unroll
            for (int j = 0; j < 4; j++) {
                int col = ncol + j * 8 + t4 * 2;
                atomicAdd(dst + col,     acc[i][j][half * 2 + 0]);
                atomicAdd(dst + col + 1, acc[i][j][half * 2 + 1]);
            }
        }
    }
}

// ================= sbf_h = sbf (T,112) @ sbf_W (112,8), K-split ==================
#define SBF_PITCH 57
#define SBF2_WS   0
#define SBF2_TILE 3584
#define SBF2_SMEM (SBF2_TILE + 256 * SBF_PITCH * 4)

__global__ void __launch_bounds__(256)
sbf_fast2(const float* __restrict__ sbf, const float* __restrict__ sbfW,
          float* __restrict__ out, int T)
{
    extern __shared__ char smemc[];
    float* Ws = (float*)(smemc + SBF2_WS);       // [112][8] (same layout as sbfW)
    float* tile = (float*)(smemc + SBF2_TILE);   // [256][57]
    const int tid = threadIdx.x;
    const int t0 = blockIdx.x * 256;
    if (tid < 224) *(float4*)&Ws[tid * 4] = *(const float4*)&sbfW[tid * 4];

    float acc[NB];
#pragma unroll
    for (int o = 0; o < NB; o++) acc[o] = 0.f;

#pragma unroll
    for (int half = 0; half < 2; half++) {
        __syncthreads();
#pragma unroll
        for (int i = 0; i < 14; i++) {
            int idx = i * 256 + tid;
            int r = idx / 14, c = idx % 14;
            int t = t0 + r;
            float4 v = (t < T) ? *(const float4*)&sbf[(size_t)t * NSR + half * 56 + c * 4]
                               : make_float4(0.f, 0.f, 0.f, 0.f);
            tile[r * SBF_PITCH + c * 4 + 0] = v.x;
            tile[r * SBF_PITCH + c * 4 + 1] = v.y;
            tile[r * SBF_PITCH + c * 4 + 2] = v.z;
            tile[r * SBF_PITCH + c * 4 + 3] = v.w;
        }
        __syncthreads();
        const float* myrow = &tile[tid * SBF_PITCH];
#pragma unroll 4
        for (int k = 0; k < 56; k++) {
            float s = myrow[k];
            float4 w0 = *(const float4*)&Ws[(half * 56 + k) * 8];
            float4 w1 = *(const float4*)&Ws[(half * 56 + k) * 8 + 4];
            acc[0] = fmaf(s, w0.x, acc[0]); acc[1] = fmaf(s, w0.y, acc[1]);
            acc[2] = fmaf(s, w0.z, acc[2]); acc[3] = fmaf(s, w0.w, acc[3]);
            acc[4] = fmaf(s, w1.x, acc[4]); acc[5] = fmaf(s, w1.y, acc[5]);
            acc[6] = fmaf(s, w1.z, acc[6]); acc[7] = fmaf(s, w1.w, acc[7]);
        }
    }
    const int t = t0 + tid;
    if (t < T) {
        *(float4*)&out[(size_t)t * NB]     = make_float4(acc[0], acc[1], acc[2], acc[3]);
        *(float4*)&out[(size_t)t * NB + 4] = make_float4(acc[4], acc[5], acc[6], acc[7]);
    }
}

// ================= weight prep ===================================================
struct W9 { const float* p[9]; };
__global__ void transpose_w(W9 ws, float* __restrict__ out)
{
    int w = blockIdx.y;
    const float* in = ws.p[w];
    float* o = out + (size_t)w * H * H;
    int idx = blockIdx.x * 256 + threadIdx.x;
    int n = idx >> 7, k = idx & 127;
    o[n * H + k] = tf32r(in[k * H + n]);
}
__global__ void round_bilw(const float* __restrict__ in, float* __restrict__ out)
{
    int idx = blockIdx.x * 256 + threadIdx.x;
    if (idx < H * NB * H) out[idx] = tf32r(in[idx]);
}

// ================= launch ========================================================
extern "C" void kernel_launch(void* const* d_in, const int* in_sizes, int n_in,
                              void* d_out, int out_size)
{
    const float* x      = (const float*)d_in[0];
    const float* rbf    = (const float*)d_in[1];
    const float* sbf    = (const float*)d_in[2];
    const int*   kj     = (const int*)  d_in[3];
    const int*   ji     = (const int*)  d_in[4];
    const float* rbf_W  = (const float*)d_in[5];
    const float* sbf_W  = (const float*)d_in[6];
    const float* ji_W   = (const float*)d_in[7];
    const float* ji_b   = (const float*)d_in[8];
    const float* kj_W   = (const float*)d_in[9];
    const float* kj_b   = (const float*)d_in[10];
    const float* bil_W  = (const float*)d_in[11];
    const float* pre_b1 = (const float*)d_in[13];
    const float* pre_b2 = (const float*)d_in[15];
    const float* pre_b3 = (const float*)d_in[17];
    const float* post_b1 = (const float*)d_in[19];
    const float* post_b2 = (const float*)d_in[21];
    const float* post_b3 = (const float*)d_in[23];
    const float* post_b4 = (const float*)d_in[25];
    float* out = (float*)d_out;

    const int E = in_sizes[0] / H;
    const int T = in_sizes[3];

    float *p_h, *p_xkj, *p_sbfh, *p_wt, *p_bw;
    cudaGetSymbolAddress((void**)&p_h,    g_h);
    cudaGetSymbolAddress((void**)&p_xkj,  g_xkj);
    cudaGetSymbolAddress((void**)&p_sbfh, g_sbfh);
    cudaGetSymbolAddress((void**)&p_wt,   g_wt);
    cudaGetSymbolAddress((void**)&p_bw,   g_bw);

    cudaFuncSetAttribute(fused_jikj, cudaFuncAttributeMaxDynamicSharedMemorySize, FJ_SMEM);
    cudaFuncSetAttribute(fused_pre,  cudaFuncAttributeMaxDynamicSharedMemorySize, FP_SMEM);
    cudaFuncSetAttribute(fused_post, cudaFuncAttributeMaxDynamicSharedMemorySize, FP_SMEM);
    cudaFuncSetAttribute(triplet_fused, cudaFuncAttributeMaxDynamicSharedMemorySize, TR_SMEM);
    cudaFuncSetAttribute(sbf_fast2, cudaFuncAttributeMaxDynamicSharedMemorySize, SBF2_SMEM);

    const int gE = (E + 127) / 128;
    const int gT = (T + 127) / 128;

    // 0. weight prep
    W9 ws;
    ws.p[0] = ji_W; ws.p[1] = kj_W;
    ws.p[2] = (const float*)d_in[12]; ws.p[3] = (const float*)d_in[14]; ws.p[4] = (const float*)d_in[16];
    ws.p[5] = (const float*)d_in[18]; ws.p[6] = (const float*)d_in[20];
    ws.p[7] = (const float*)d_in[22]; ws.p[8] = (const float*)d_in[24];
    transpose_w<<<dim3(64, 9), 256>>>(ws, p_wt);
    round_bilw<<<(H * NB * H + 255) / 256, 256>>>(bil_W, p_bw);

    // 1. sbf_h
    sbf_fast2<<<(T + 255) / 256, 256, SBF2_SMEM>>>(sbf, sbf_W, p_sbfh, T);
    // 2. x_kj -> g_xkj, x_ji -> g_h (+ in-smem rbf_h)
    fused_jikj<<<gE, 512, FJ_SMEM>>>(x, rbf, rbf_W,
                                     p_wt + 1 * H * H, kj_b,
                                     p_wt + 0 * H * H, ji_b,
                                     p_xkj, p_h, E);
    // 3. triplet bilinear + scatter-add into g_h
    triplet_fused<<<gT, 512, TR_SMEM>>>(p_xkj, p_sbfh, kj, ji, p_bw, p_h, T);
    // 4. pre-chain (3 GEMMs fused): g_h -> g_h (in-place per CTA slice)
    fused_pre<<<gE, 512, FP_SMEM>>>(p_h, x,
                                    p_wt + 2 * H * H, pre_b1,
                                    p_wt + 3 * H * H, pre_b2,
                                    p_wt + 4 * H * H, pre_b3,
                                    p_h, E);
    // 5. post-chain (4 GEMMs fused): g_h -> out
    fused_post<<<gE, 512, FP_SMEM>>>(p_h,
                                     p_wt + 5 * H * H, post_b1,
                                     p_wt + 6 * H * H, post_b2,
                                     p_wt + 7 * H * H, post_b3,
                                     p_wt + 8 * H * H, post_b4,
                                     out, E);
}